// round 5
// baseline (speedup 1.0000x reference)
#include <cuda_runtime.h>

// Problem constants (fixed shapes from reference)
#define B_    8
#define DIM   64
#define HID   128
#define HH    192
#define WW    192
#define HW    (HH*WW)          // 36864
#define TS    16               // interior tile
#define PAD   18               // TS + 2 halo
#define NPIX  (PAD*PAD)        // 324
#define CH    32               // hid channels per chunk
#define NPAIR (CH/2)           // 16 pairs per chunk
#define NCHK  (HID/CH)         // 4 chunks

typedef unsigned long long ull;

// packed f32x2 helpers (ptxas never emits these from C++ — PTX only)
__device__ __forceinline__ ull ffma2(ull a, ull b, ull c) {
    ull d;
    asm("fma.rn.f32x2 %0, %1, %2, %3;" : "=l"(d) : "l"(a), "l"(b), "l"(c));
    return d;
}
__device__ __forceinline__ ull mul2(ull a, ull b) {
    ull d;
    asm("mul.rn.f32x2 %0, %1, %2;" : "=l"(d) : "l"(a), "l"(b));
    return d;
}
__device__ __forceinline__ ull pack2(float x) {           // (x, x)
    ull r;
    asm("mov.b64 %0, {%1, %1};" : "=l"(r) : "f"(x));
    return r;
}
__device__ __forceinline__ void unpack2(ull v, float& lo, float& hi) {
    asm("mov.b64 {%0, %1}, %2;" : "=f"(lo), "=f"(hi) : "l"(v));
}

// Scratch (no device mallocs allowed)
__device__ float g_xmean[B_*DIM];
__device__ float g_ker[B_*HID*9];

// ---------------------------------------------------------------------------
// Kernel 1: per-(b,c) spatial mean of x.
// ---------------------------------------------------------------------------
__global__ void k_mean(const float* __restrict__ x) {
    int bc = blockIdx.x;
    const float4* p = (const float4*)(x + (size_t)bc * HW);
    float s = 0.f;
    #pragma unroll 4
    for (int i = threadIdx.x; i < HW/4; i += 256) {
        float4 v = p[i];
        s += (v.x + v.y) + (v.z + v.w);
    }
    __shared__ float red[8];
    #pragma unroll
    for (int o = 16; o; o >>= 1) s += __shfl_down_sync(0xffffffffu, s, o);
    if ((threadIdx.x & 31) == 0) red[threadIdx.x >> 5] = s;
    __syncthreads();
    if (threadIdx.x < 32) {
        s = (threadIdx.x < 8) ? red[threadIdx.x] : 0.f;
        #pragma unroll
        for (int o = 4; o; o >>= 1) s += __shfl_down_sync(0xffffffffu, s, o);
        if (threadIdx.x == 0) g_xmean[bc] = s * (1.0f / (float)HW);
    }
}

// ---------------------------------------------------------------------------
// Kernel 2: dynamic 3x3 kernel generation (mean(h) = w_in @ mean(x) + b_in).
// ---------------------------------------------------------------------------
__global__ void k_gen(const float* __restrict__ w_in, const float* __restrict__ b_in,
                      const float* __restrict__ wg1,  const float* __restrict__ bg1,
                      const float* __restrict__ wg2,  const float* __restrict__ bg2) {
    int b = blockIdx.x;
    int t = threadIdx.x;  // 0..127
    __shared__ float xm[DIM], g0[HID], g1[HID];
    if (t < DIM) xm[t] = g_xmean[b*DIM + t];
    __syncthreads();
    {
        float s = b_in[t];
        #pragma unroll 8
        for (int c = 0; c < DIM; c++) s = fmaf(w_in[t*DIM + c], xm[c], s);
        g0[t] = s;
    }
    __syncthreads();
    {
        float s = bg1[t];
        #pragma unroll 8
        for (int c = 0; c < HID; c++) s = fmaf(wg1[t*HID + c], g0[c], s);
        g1[t] = s > 0.f ? s : 0.f;
    }
    __syncthreads();
    #pragma unroll
    for (int tt = 0; tt < 9; tt++) {
        int row = t*9 + tt;
        float s = bg2[row];
        #pragma unroll 8
        for (int c = 0; c < HID; c++) s = fmaf(wg2[row*HID + c], g1[c], s);
        g_ker[b*HID*9 + row] = s;
    }
}

// ---------------------------------------------------------------------------
// Kernel 3: fused pipeline, hid-chunked (4 x 32 channels) so smem fits
// 2 CTAs/SM. h stored as interleaved f32x2 hid-pairs; depthwise in f32x2.
//
// SMEM (floats):
//   sh_win  [DIM*HID = 8192]  w_in^T  [c][hid]
//   sh_wout [HID*64 = 8192]   w_out   [hid][o]
//   sh_ker2 [64*9*2 = 1152]   paired dyn kernels (ull)
//   sh_bin [128], sh_bout [64]
//   sh_h    [NPAIR*NPIX ull = 16*324*2 floats = 10368]
// total = 28104 floats = 112416 B? -> compute exactly below (~110.6KB)
// ---------------------------------------------------------------------------
extern __shared__ float smem[];

__global__ __launch_bounds__(256, 2)
void k_main(const float* __restrict__ x,
            const float* __restrict__ w_in,  const float* __restrict__ b_in,
            const float* __restrict__ w_out, const float* __restrict__ b_out,
            float* __restrict__ out) {
    float* sh_win  = smem;                       // 8192
    float* sh_wout = sh_win + DIM*HID;           // 8192
    ull*   sh_ker2 = (ull*)(sh_wout + HID*64);   // 576 ull = 1152 f
    float* sh_bin  = (float*)(sh_ker2 + 64*9);   // 128
    float* sh_bout = sh_bin + HID;               // 64
    ull*   sh_h    = (ull*)(sh_bout + 64);       // NPAIR*NPIX ull

    const int tid = threadIdx.x;
    const int b   = blockIdx.z;
    const int tx0 = blockIdx.x * TS, ty0 = blockIdx.y * TS;

    // --- stage weights (transposed), kernels (paired), biases ---
    for (int i = tid; i < HID*DIM; i += 256) {
        int o = i / DIM, c = i % DIM;
        sh_win[c*HID + o] = w_in[i];
    }
    for (int i = tid; i < 64*HID; i += 256) {
        int o = i / HID, hid = i % HID;
        sh_wout[hid*64 + o] = w_out[i];
    }
    {
        const float* kb = g_ker + b*HID*9;
        for (int i = tid; i < 64*9; i += 256) {      // pair p, tap t
            int p = i / 9, t = i % 9;
            float lo = kb[(2*p)*9 + t], hi = kb[(2*p+1)*9 + t];
            ull v;
            asm("mov.b64 %0, {%1, %2};" : "=l"(v) : "f"(lo), "f"(hi));
            sh_ker2[i] = v;
        }
    }
    if (tid < HID) sh_bin[tid]  = b_in[tid];
    if (tid < 64)  sh_bout[tid] = b_out[tid];
    __syncthreads();

    const float* xb = x + (size_t)b * DIM * HW;

    // persistent projection accumulators (64 out channels as 32 pairs)
    ull pacc[32];
    {
        const ull* bop = (const ull*)sh_bout;
        #pragma unroll
        for (int i = 0; i < 32; i++) pacc[i] = bop[i];
    }

    const int ix = tid & 15, iy = tid >> 4;
    const int ctr = (iy + 1)*PAD + (ix + 1);     // interior pixel index
    const ull ABSM = 0x7fffffff7fffffffULL;
    const ull C55 = pack2(0.55f), C45 = pack2(0.45f);

    #pragma unroll 1
    for (int ch = 0; ch < NCHK; ch++) {
        const int hb = ch * CH;

        // ---------------- Phase 1: h chunk into SMEM (paired) ----------------
        #pragma unroll 1
        for (int it = 0; it < 2; it++) {
            int pp = tid + it*256;
            if (pp >= NPIX) break;
            int py = pp / PAD, px = pp % PAD;
            int gy = ty0 + py - 1, gx = tx0 + px - 1;
            bool valid = (gy >= 0) & (gy < HH) & (gx >= 0) & (gx < WW);

            ull acc[NPAIR];
            const ull* bp = (const ull*)(sh_bin + hb);
            #pragma unroll
            for (int i = 0; i < NPAIR; i++) acc[i] = valid ? bp[i] : 0ull;

            const float* xp = xb + gy*WW + gx;
            const float* wbase = sh_win + hb;
            #pragma unroll 4
            for (int c = 0; c < DIM; c++) {
                float xc = valid ? __ldg(xp + (size_t)c * HW) : 0.f;
                ull xx = pack2(xc);
                const ulonglong2* wp = (const ulonglong2*)(wbase + c*HID);
                #pragma unroll
                for (int j = 0; j < NPAIR/2; j++) {
                    ulonglong2 w2 = wp[j];
                    acc[2*j]   = ffma2(w2.x, xx, acc[2*j]);
                    acc[2*j+1] = ffma2(w2.y, xx, acc[2*j+1]);
                }
            }
            #pragma unroll
            for (int i = 0; i < NPAIR; i++) sh_h[i*NPIX + pp] = acc[i];
        }
        __syncthreads();

        // ------- Phase 2: paired depthwise 3x3 + LeakyReLU + projection ------
        #pragma unroll 1
        for (int i = 0; i < NPAIR; i++) {
            const int gp = ch*NPAIR + i;                 // global pair
            const ull* hp = sh_h + i*NPIX + ctr;
            const ull* kp = sh_ker2 + gp*9;

            ull s;
            s = mul2 (kp[0], hp[-PAD-1]);
            s = ffma2(kp[1], hp[-PAD  ], s);
            s = ffma2(kp[2], hp[-PAD+1], s);
            s = ffma2(kp[3], hp[-1    ], s);
            s = ffma2(kp[4], hp[ 0    ], s);
            s = ffma2(kp[5], hp[ 1    ], s);
            s = ffma2(kp[6], hp[ PAD-1], s);
            s = ffma2(kp[7], hp[ PAD  ], s);
            s = ffma2(kp[8], hp[ PAD+1], s);
            // LeakyReLU(0.1) packed: 0.55*s + 0.45*|s|
            ull y2 = ffma2(s & ABSM, C45, mul2(s, C55));

            float ylo, yhi;
            unpack2(y2, ylo, yhi);
            ull ylo2 = pack2(ylo), yhi2 = pack2(yhi);

            const ulonglong2* w0 = (const ulonglong2*)(sh_wout + (2*gp  )*64);
            const ulonglong2* w1 = (const ulonglong2*)(sh_wout + (2*gp+1)*64);
            #pragma unroll
            for (int q = 0; q < 16; q++) {
                ulonglong2 a = w0[q];
                pacc[2*q]   = ffma2(a.x, ylo2, pacc[2*q]);
                pacc[2*q+1] = ffma2(a.y, ylo2, pacc[2*q+1]);
            }
            #pragma unroll
            for (int q = 0; q < 16; q++) {
                ulonglong2 a = w1[q];
                pacc[2*q]   = ffma2(a.x, yhi2, pacc[2*q]);
                pacc[2*q+1] = ffma2(a.y, yhi2, pacc[2*q+1]);
            }
        }
        __syncthreads();   // before next chunk overwrites sh_h
    }

    // ------------------------------ store out ------------------------------
    {
        const int gy = ty0 + iy, gx = tx0 + ix;
        float* op = out + (size_t)b * DIM * HW + gy*WW + gx;
        #pragma unroll
        for (int j = 0; j < 32; j++) {
            float lo, hi;
            unpack2(pacc[j], lo, hi);
            op[(size_t)(2*j    ) * HW] = lo;
            op[(size_t)(2*j + 1) * HW] = hi;
        }
    }
}

// ---------------------------------------------------------------------------
extern "C" void kernel_launch(void* const* d_in, const int* in_sizes, int n_in,
                              void* d_out, int out_size) {
    const float* x     = (const float*)d_in[0];
    const float* w_in  = (const float*)d_in[1];
    const float* b_in  = (const float*)d_in[2];
    const float* wg1   = (const float*)d_in[3];
    const float* bg1   = (const float*)d_in[4];
    const float* wg2   = (const float*)d_in[5];
    const float* bg2   = (const float*)d_in[6];
    const float* w_out = (const float*)d_in[7];
    const float* b_out = (const float*)d_in[8];
    float* out = (float*)d_out;

    // floats: 8192 + 8192 + 1152 + 128 + 64 + NPAIR*NPIX*2
    const int SMEM_BYTES = (8192 + 8192 + 1152 + 128 + 64 + NPAIR*NPIX*2) * 4; // 111,488 B
    cudaFuncSetAttribute(k_main, cudaFuncAttributeMaxDynamicSharedMemorySize, SMEM_BYTES);

    k_mean<<<B_*DIM, 256>>>(x);
    k_gen<<<B_, HID>>>(w_in, b_in, wg1, bg1, wg2, bg2);
    dim3 grid(WW/TS, HH/TS, B_);
    k_main<<<grid, 256, SMEM_BYTES>>>(x, w_in, b_in, w_out, b_out, out);
}

// round 6
// speedup vs baseline: 1.0444x; 1.0444x over previous
#include <cuda_runtime.h>

// Problem constants
#define B_     8
#define DIM    64
#define HID    128
#define HH     192
#define WW     192
#define HW     (HH*WW)         // 36864
#define TS     16
#define PAD    18
#define NPIX   (PAD*PAD)       // 324
#define NTILX  (WW/TS)         // 12
#define NTILY  (HH/TS)         // 12
#define NTILES (NTILX*NTILY*B_) // 1152

typedef unsigned long long ull;

__device__ __forceinline__ ull ffma2(ull a, ull b, ull c) {
    ull d;
    asm("fma.rn.f32x2 %0, %1, %2, %3;" : "=l"(d) : "l"(a), "l"(b), "l"(c));
    return d;
}
__device__ __forceinline__ ull mul2(ull a, ull b) {
    ull d;
    asm("mul.rn.f32x2 %0, %1, %2;" : "=l"(d) : "l"(a), "l"(b));
    return d;
}
__device__ __forceinline__ ull pack2(float x) {
    ull r;
    asm("mov.b64 %0, {%1, %1};" : "=l"(r) : "f"(x));
    return r;
}
__device__ __forceinline__ ull pack2b(float lo, float hi) {
    ull r;
    asm("mov.b64 %0, {%1, %2};" : "=l"(r) : "f"(lo), "f"(hi));
    return r;
}
__device__ __forceinline__ void unpack2(ull v, float& lo, float& hi) {
    asm("mov.b64 {%0, %1}, %2;" : "=f"(lo), "=f"(hi) : "l"(v));
}

// Scratch + barrier state (no device mallocs allowed; zero-initialized)
__device__ float g_xmean[B_*DIM];
__device__ float g_ker[B_*HID*9];
__device__ unsigned g_bar1, g_bar2, g_done;

// Software global barrier: all CTAs are resident (grid = #SMs, 1 CTA/SM by smem).
__device__ __forceinline__ void gbar(unsigned* bar, unsigned NB, int tid) {
    if (tid == 0) {
        __threadfence();
        atomicAdd(bar, 1u);
        while (atomicAdd(bar, 0u) < NB) __nanosleep(128);
    }
    __syncthreads();
    __threadfence();
}

extern __shared__ float smem[];

// SMEM layout (floats):
//   sh_w    [8192]  phase1: w_in^T [c][hid] / phase2: w_out [hid][o]
//   sh_ker2 [1152]  paired dyn kernels (576 ull)
//   sh_bin  [128], sh_bout [64]
//   sh_h    [41472] h tile as 64 hid-pairs x 324 pixels (ull)
// total 204,032 B dynamic.
__global__ __launch_bounds__(256, 1)
void k_all(const float* __restrict__ x,
           const float* __restrict__ w_in,  const float* __restrict__ b_in,
           const float* __restrict__ wg1,   const float* __restrict__ bg1,
           const float* __restrict__ wg2,   const float* __restrict__ bg2,
           const float* __restrict__ w_out, const float* __restrict__ b_out,
           float* __restrict__ out) {
    const int tid = threadIdx.x;
    const unsigned NB = gridDim.x;

    // =================== Phase A: per-(b,c) spatial means ===================
    {
        __shared__ float red[8];
        for (int bc = blockIdx.x; bc < B_*DIM; bc += (int)NB) {
            const float4* p = (const float4*)(x + (size_t)bc * HW);
            float s = 0.f;
            #pragma unroll 4
            for (int i = tid; i < HW/4; i += 256) {
                float4 v = p[i];
                s += (v.x + v.y) + (v.z + v.w);
            }
            #pragma unroll
            for (int o = 16; o; o >>= 1) s += __shfl_down_sync(0xffffffffu, s, o);
            if ((tid & 31) == 0) red[tid >> 5] = s;
            __syncthreads();
            if (tid < 32) {
                s = (tid < 8) ? red[tid] : 0.f;
                #pragma unroll
                for (int o = 4; o; o >>= 1) s += __shfl_down_sync(0xffffffffu, s, o);
                if (tid == 0) g_xmean[bc] = s * (1.0f / (float)HW);
            }
            __syncthreads();
        }
    }
    gbar(&g_bar1, NB, tid);

    // =================== Phase B: dynamic kernel generation =================
    if (blockIdx.x < B_) {
        const int b = blockIdx.x;
        __shared__ float xm[DIM], g0[HID], g1[HID];
        if (tid < DIM) xm[tid] = g_xmean[b*DIM + tid];
        __syncthreads();
        if (tid < HID) {
            float s = b_in[tid];
            #pragma unroll 8
            for (int c = 0; c < DIM; c++) s = fmaf(w_in[tid*DIM + c], xm[c], s);
            g0[tid] = s;   // == spatial mean of h[b, tid] (mean is linear)
        }
        __syncthreads();
        if (tid < HID) {
            float s = bg1[tid];
            #pragma unroll 8
            for (int c = 0; c < HID; c++) s = fmaf(wg1[tid*HID + c], g0[c], s);
            g1[tid] = s > 0.f ? s : 0.f;
        }
        __syncthreads();
        if (tid < HID) {
            #pragma unroll
            for (int tt = 0; tt < 9; tt++) {
                int row = tid*9 + tt;
                float s = bg2[row];
                #pragma unroll 8
                for (int c = 0; c < HID; c++) s = fmaf(wg2[row*HID + c], g1[c], s);
                g_ker[b*HID*9 + row] = s;
            }
        }
    }
    gbar(&g_bar2, NB, tid);

    // ======================= Phase C: fused main loop =======================
    float* sh_w    = smem;                         // 8192 f
    ull*   sh_ker2 = (ull*)(smem + 8192);          // 576 ull
    float* sh_bin  = (float*)(sh_ker2 + 64*9);     // 128
    float* sh_bout = sh_bin + HID;                 // 64
    ull*   sh_h    = (ull*)(sh_bout + 64);         // 64*NPIX ull

    if (tid < HID) sh_bin[tid]  = b_in[tid];
    if (tid < 64)  sh_bout[tid] = b_out[tid];

    const int ix = tid & 15, iy = tid >> 4;
    const int ctr = (iy + 1)*PAD + (ix + 1);
    const ull ABSM = 0x7fffffff7fffffffULL;
    const ull C55 = pack2(0.55f), C45 = pack2(0.45f);

    #pragma unroll 1
    for (int t = blockIdx.x; t < NTILES; t += (int)NB) {
        const int b   = t / (NTILX*NTILY);
        const int r   = t - b*(NTILX*NTILY);
        const int ty0 = (r / NTILX)*TS;
        const int tx0 = (r % NTILX)*TS;

        // stage this sample's paired kernels + w_in^T
        {
            const float* kb = g_ker + b*HID*9;
            for (int i = tid; i < 64*9; i += 256) {
                int p = i / 9, tt = i - p*9;
                sh_ker2[i] = pack2b(kb[(2*p)*9 + tt], kb[(2*p+1)*9 + tt]);
            }
            for (int i = tid; i < HID*DIM; i += 256) {
                int o = i >> 6, c = i & 63;
                sh_w[c*HID + o] = w_in[i];
            }
        }
        __syncthreads();

        // ---------------- Phase 1: h (paired) into SMEM ----------------
        const float* xb = x + (size_t)b * DIM * HW;
        #pragma unroll 1
        for (int it = 0; it < 2; it++) {
            int pp = tid + it*256;
            if (pp >= NPIX) break;
            int py = pp / PAD, px = pp - py*PAD;
            int gy = ty0 + py - 1, gx = tx0 + px - 1;
            bool valid = (gy >= 0) & (gy < HH) & (gx >= 0) & (gx < WW);

            float xv[DIM];
            const float* xp = xb + gy*WW + gx;
            #pragma unroll
            for (int c = 0; c < DIM; c++) xv[c] = valid ? __ldg(xp + (size_t)c * HW) : 0.f;

            #pragma unroll 1
            for (int hb = 0; hb < HID; hb += 32) {
                ull acc[16];
                const ull* bp = (const ull*)(sh_bin + hb);
                #pragma unroll
                for (int i = 0; i < 16; i++) acc[i] = valid ? bp[i] : 0ull;

                const float* wbase = sh_w + hb;
                #pragma unroll 8
                for (int c = 0; c < DIM; c++) {
                    ull xx = pack2(xv[c]);
                    const ulonglong2* wp = (const ulonglong2*)(wbase + c*HID);
                    #pragma unroll
                    for (int j = 0; j < 8; j++) {
                        ulonglong2 w2 = wp[j];
                        acc[2*j]   = ffma2(w2.x, xx, acc[2*j]);
                        acc[2*j+1] = ffma2(w2.y, xx, acc[2*j+1]);
                    }
                }
                ull* hdst = sh_h + (hb >> 1)*NPIX + pp;
                #pragma unroll
                for (int i = 0; i < 16; i++) hdst[i*NPIX] = acc[i];
            }
        }
        __syncthreads();

        // swap sh_w -> w_out [hid][o]
        for (int i = tid; i < 64*HID; i += 256) {
            int o = i >> 7, hid = i & 127;
            sh_w[hid*64 + o] = w_out[i];
        }
        __syncthreads();

        // ---- Phase 2: paired depthwise 3x3 + LeakyReLU + projection ----
        {
            ull pacc[32];
            const ull* bop = (const ull*)sh_bout;
            #pragma unroll
            for (int i = 0; i < 32; i++) pacc[i] = bop[i];

            #pragma unroll 2
            for (int p = 0; p < 64; p++) {
                const ull* hp = sh_h + p*NPIX + ctr;
                const ull* kp = sh_ker2 + p*9;

                ull s;
                s = mul2 (kp[0], hp[-PAD-1]);
                s = ffma2(kp[1], hp[-PAD  ], s);
                s = ffma2(kp[2], hp[-PAD+1], s);
                s = ffma2(kp[3], hp[-1    ], s);
                s = ffma2(kp[4], hp[ 0    ], s);
                s = ffma2(kp[5], hp[ 1    ], s);
                s = ffma2(kp[6], hp[ PAD-1], s);
                s = ffma2(kp[7], hp[ PAD  ], s);
                s = ffma2(kp[8], hp[ PAD+1], s);
                // LeakyReLU(0.1) packed: 0.55*s + 0.45*|s|
                ull y2 = ffma2(s & ABSM, C45, mul2(s, C55));

                float ylo, yhi;
                unpack2(y2, ylo, yhi);
                ull ylo2 = pack2(ylo), yhi2 = pack2(yhi);

                const ulonglong2* w0 = (const ulonglong2*)(sh_w + (2*p  )*64);
                const ulonglong2* w1 = (const ulonglong2*)(sh_w + (2*p+1)*64);
                #pragma unroll
                for (int q = 0; q < 16; q++) {
                    ulonglong2 a = w0[q];
                    pacc[2*q]   = ffma2(a.x, ylo2, pacc[2*q]);
                    pacc[2*q+1] = ffma2(a.y, ylo2, pacc[2*q+1]);
                }
                #pragma unroll
                for (int q = 0; q < 16; q++) {
                    ulonglong2 a = w1[q];
                    pacc[2*q]   = ffma2(a.x, yhi2, pacc[2*q]);
                    pacc[2*q+1] = ffma2(a.y, yhi2, pacc[2*q+1]);
                }
            }

            const int gy = ty0 + iy, gx = tx0 + ix;
            float* op = out + (size_t)b * DIM * HW + gy*WW + gx;
            #pragma unroll
            for (int j = 0; j < 32; j++) {
                float lo, hi;
                unpack2(pacc[j], lo, hi);
                op[(size_t)(2*j    ) * HW] = lo;
                op[(size_t)(2*j + 1) * HW] = hi;
            }
        }
        __syncthreads();   // before next tile restages sh_w / sh_ker2 / sh_h
    }

    // reset barrier state for the next graph replay (last CTA to finish)
    if (tid == 0) {
        __threadfence();
        if (atomicAdd(&g_done, 1u) == NB - 1u) {
            atomicExch(&g_bar1, 0u);
            atomicExch(&g_bar2, 0u);
            atomicExch(&g_done, 0u);
        }
    }
}

// ---------------------------------------------------------------------------
extern "C" void kernel_launch(void* const* d_in, const int* in_sizes, int n_in,
                              void* d_out, int out_size) {
    const float* x     = (const float*)d_in[0];
    const float* w_in  = (const float*)d_in[1];
    const float* b_in  = (const float*)d_in[2];
    const float* wg1   = (const float*)d_in[3];
    const float* bg1   = (const float*)d_in[4];
    const float* wg2   = (const float*)d_in[5];
    const float* bg2   = (const float*)d_in[6];
    const float* w_out = (const float*)d_in[7];
    const float* b_out = (const float*)d_in[8];
    float* out = (float*)d_out;

    int dev = 0, nsm = 148;
    cudaGetDevice(&dev);
    cudaDeviceGetAttribute(&nsm, cudaDevAttrMultiProcessorCount, dev);

    const int SMEM_BYTES = (8192 + 1152 + 128 + 64 + 64*NPIX*2) * 4; // 204,032 B
    cudaFuncSetAttribute(k_all, cudaFuncAttributeMaxDynamicSharedMemorySize, SMEM_BYTES);

    k_all<<<nsm, 256, SMEM_BYTES>>>(x, w_in, b_in, wg1, bg1, wg2, bg2, w_out, b_out, out);
}

// round 7
// speedup vs baseline: 1.0546x; 1.0098x over previous
#include <cuda_runtime.h>

// Problem constants
#define B_     8
#define DIM    64
#define HID    128
#define HH     192
#define WW     192
#define HW     (HH*WW)          // 36864
#define TS     16
#define PAD    18
#define NPIX   (PAD*PAD)        // 324
#define NTILX  (WW/TS)          // 12
#define NTILY  (HH/TS)          // 12
#define NTILES (NTILX*NTILY*B_) // 1152
#define NT     512              // threads per CTA

typedef unsigned long long ull;

__device__ __forceinline__ ull ffma2(ull a, ull b, ull c) {
    ull d;
    asm("fma.rn.f32x2 %0, %1, %2, %3;" : "=l"(d) : "l"(a), "l"(b), "l"(c));
    return d;
}
__device__ __forceinline__ ull mul2(ull a, ull b) {
    ull d;
    asm("mul.rn.f32x2 %0, %1, %2;" : "=l"(d) : "l"(a), "l"(b));
    return d;
}
__device__ __forceinline__ ull add2(ull a, ull b) {
    ull d;
    asm("add.rn.f32x2 %0, %1, %2;" : "=l"(d) : "l"(a), "l"(b));
    return d;
}
__device__ __forceinline__ ull pack2(float x) {
    ull r;
    asm("mov.b64 %0, {%1, %1};" : "=l"(r) : "f"(x));
    return r;
}
__device__ __forceinline__ ull pack2b(float lo, float hi) {
    ull r;
    asm("mov.b64 %0, {%1, %2};" : "=l"(r) : "f"(lo), "f"(hi));
    return r;
}
__device__ __forceinline__ void unpack2(ull v, float& lo, float& hi) {
    asm("mov.b64 {%0, %1}, %2;" : "=f"(lo), "=f"(hi) : "l"(v));
}

// Scratch + barrier state (no device mallocs allowed; zero-initialized)
__device__ float g_xmean[B_*DIM];
__device__ float g_ker[B_*HID*9];
__device__ unsigned g_bar1, g_bar2, g_done;

// Software global barrier (all CTAs resident: grid = #SMs, 1 CTA/SM by smem)
__device__ __forceinline__ void gbar(unsigned* bar, unsigned NB, int tid) {
    if (tid == 0) {
        __threadfence();
        atomicAdd(bar, 1u);
        while (atomicAdd(bar, 0u) < NB) __nanosleep(128);
    }
    __syncthreads();
    __threadfence();
}

extern __shared__ float smem[];

// SMEM layout (floats):
//   sh_w    [8192]  phase1: w_in^T [c][hid] / phase2: w_out [hid][o]
//   sh_ker2 [1152]  paired dyn kernels (576 ull)
//   sh_bin  [128], sh_bout [64]
//   sh_h    [41472] h tile: 64 hid-pairs x 324 pixels (ull); reused as the
//                   phase-2 reduction buffer (32 ull x 256 pix) after a sync.
__global__ __launch_bounds__(NT, 1)
void k_all(const float* __restrict__ x,
           const float* __restrict__ w_in,  const float* __restrict__ b_in,
           const float* __restrict__ wg1,   const float* __restrict__ bg1,
           const float* __restrict__ wg2,   const float* __restrict__ bg2,
           const float* __restrict__ w_out, const float* __restrict__ b_out,
           float* __restrict__ out) {
    const int tid = threadIdx.x;
    const unsigned NB = gridDim.x;

    // =================== Phase A: per-(b,c) spatial means ===================
    {
        __shared__ float redw[16];
        for (int bc = blockIdx.x; bc < B_*DIM; bc += (int)NB) {
            const float4* p = (const float4*)(x + (size_t)bc * HW);
            float s = 0.f;
            #pragma unroll 4
            for (int i = tid; i < HW/4; i += NT) {
                float4 v = p[i];
                s += (v.x + v.y) + (v.z + v.w);
            }
            #pragma unroll
            for (int o = 16; o; o >>= 1) s += __shfl_down_sync(0xffffffffu, s, o);
            if ((tid & 31) == 0) redw[tid >> 5] = s;
            __syncthreads();
            if (tid < 32) {
                s = (tid < 16) ? redw[tid] : 0.f;
                #pragma unroll
                for (int o = 8; o; o >>= 1) s += __shfl_down_sync(0xffffffffu, s, o);
                if (tid == 0) g_xmean[bc] = s * (1.0f / (float)HW);
            }
            __syncthreads();
        }
    }
    gbar(&g_bar1, NB, tid);

    // =================== Phase B: dynamic kernel generation =================
    if (blockIdx.x < B_) {
        const int b = blockIdx.x;
        __shared__ float xm[DIM], g0[HID], g1[HID];
        if (tid < DIM) xm[tid] = g_xmean[b*DIM + tid];
        __syncthreads();
        if (tid < HID) {
            float s = b_in[tid];
            #pragma unroll 8
            for (int c = 0; c < DIM; c++) s = fmaf(w_in[tid*DIM + c], xm[c], s);
            g0[tid] = s;   // == spatial mean of h[b, tid] (mean is linear)
        }
        __syncthreads();
        if (tid < HID) {
            float s = bg1[tid];
            #pragma unroll 8
            for (int c = 0; c < HID; c++) s = fmaf(wg1[tid*HID + c], g0[c], s);
            g1[tid] = s > 0.f ? s : 0.f;
        }
        __syncthreads();
        if (tid < HID) {
            #pragma unroll
            for (int tt = 0; tt < 9; tt++) {
                int row = tid*9 + tt;
                float s = bg2[row];
                #pragma unroll 8
                for (int c = 0; c < HID; c++) s = fmaf(wg2[row*HID + c], g1[c], s);
                g_ker[b*HID*9 + row] = s;
            }
        }
    }
    gbar(&g_bar2, NB, tid);

    // ======================= Phase C: fused main loop =======================
    float* sh_w    = smem;                         // 8192 f
    ull*   sh_ker2 = (ull*)(smem + 8192);          // 576 ull
    float* sh_bin  = (float*)(sh_ker2 + 64*9);     // 128
    float* sh_bout = sh_bin + HID;                 // 64
    ull*   sh_h    = (ull*)(sh_bout + 64);         // 64*NPIX ull

    if (tid < HID) sh_bin[tid]  = b_in[tid];
    if (tid < 64)  sh_bout[tid] = b_out[tid];

    const int half = tid >> 8;          // phase-2 hid half
    const int pix  = tid & 255;
    const int p_ix = pix & 15, p_iy = pix >> 4;
    const int ctr  = (p_iy + 1)*PAD + (p_ix + 1);
    const ull ABSM = 0x7fffffff7fffffffULL;
    const ull C55 = pack2(0.55f), C45 = pack2(0.45f);

    #pragma unroll 1
    for (int t = blockIdx.x; t < NTILES; t += (int)NB) {
        const int b   = t / (NTILX*NTILY);
        const int r   = t - b*(NTILX*NTILY);
        const int ty0 = (r / NTILX)*TS;
        const int tx0 = (r % NTILX)*TS;

        // stage this sample's paired kernels + w_in^T [c][hid]
        {
            const float* kb = g_ker + b*HID*9;
            for (int i = tid; i < 64*9; i += NT) {
                int p = i / 9, tt = i - p*9;
                sh_ker2[i] = pack2b(kb[(2*p)*9 + tt], kb[(2*p+1)*9 + tt]);
            }
            for (int i = tid; i < HID*DIM; i += NT) {
                int o = i >> 6, c = i & 63;
                sh_w[c*HID + o] = w_in[i];
            }
        }
        __syncthreads();

        // ------- Phase 1: h (paired) into SMEM; slot = pixel x hid-half -----
        const float* xb = x + (size_t)b * DIM * HW;
        #pragma unroll 1
        for (int it = 0; it < 2; it++) {
            int s = tid + it*NT;
            if (s >= 2*NPIX) break;
            int hh = (s >= NPIX) ? 1 : 0;
            int pp = s - hh*NPIX;
            int py = pp / PAD, px = pp - py*PAD;
            int gy = ty0 + py - 1, gx = tx0 + px - 1;
            bool valid = (gy >= 0) & (gy < HH) & (gx >= 0) & (gx < WW);

            float xv[DIM];
            const float* xp = xb + gy*WW + gx;
            #pragma unroll
            for (int c = 0; c < DIM; c++) xv[c] = valid ? __ldg(xp + (size_t)c * HW) : 0.f;

            #pragma unroll 1
            for (int k = 0; k < 2; k++) {
                const int hb = hh*64 + k*32;
                ull acc[16];
                const ull* bp = (const ull*)(sh_bin + hb);
                #pragma unroll
                for (int i = 0; i < 16; i++) acc[i] = valid ? bp[i] : 0ull;

                const float* wbase = sh_w + hb;
                #pragma unroll 8
                for (int c = 0; c < DIM; c++) {
                    ull xx = pack2(xv[c]);
                    const ulonglong2* wp = (const ulonglong2*)(wbase + c*HID);
                    #pragma unroll
                    for (int j = 0; j < 8; j++) {
                        ulonglong2 w2 = wp[j];
                        acc[2*j]   = ffma2(w2.x, xx, acc[2*j]);
                        acc[2*j+1] = ffma2(w2.y, xx, acc[2*j+1]);
                    }
                }
                ull* hdst = sh_h + (hb >> 1)*NPIX + pp;
                #pragma unroll
                for (int i = 0; i < 16; i++) hdst[i*NPIX] = acc[i];
            }
        }
        __syncthreads();

        // swap sh_w -> w_out [hid][o]
        for (int i = tid; i < 64*HID; i += NT) {
            int o = i >> 7, hid = i & 127;
            sh_w[hid*64 + o] = w_out[i];
        }
        __syncthreads();

        // --- Phase 2: paired dw 3x3 + LeakyReLU + projection (hid-split) ----
        {
            ull pacc[32];
            if (half == 0) {
                const ull* bop = (const ull*)sh_bout;
                #pragma unroll
                for (int i = 0; i < 32; i++) pacc[i] = bop[i];
            } else {
                #pragma unroll
                for (int i = 0; i < 32; i++) pacc[i] = 0ull;
            }

            const int p0 = half*32;
            #pragma unroll 2
            for (int pi = 0; pi < 32; pi++) {
                const int p = p0 + pi;
                const ull* hp = sh_h + p*NPIX + ctr;
                const ull* kp = sh_ker2 + p*9;

                ull s;
                s = mul2 (kp[0], hp[-PAD-1]);
                s = ffma2(kp[1], hp[-PAD  ], s);
                s = ffma2(kp[2], hp[-PAD+1], s);
                s = ffma2(kp[3], hp[-1    ], s);
                s = ffma2(kp[4], hp[ 0    ], s);
                s = ffma2(kp[5], hp[ 1    ], s);
                s = ffma2(kp[6], hp[ PAD-1], s);
                s = ffma2(kp[7], hp[ PAD  ], s);
                s = ffma2(kp[8], hp[ PAD+1], s);
                // LeakyReLU(0.1) packed: 0.55*s + 0.45*|s|
                ull y2 = ffma2(s & ABSM, C45, mul2(s, C55));

                float ylo, yhi;
                unpack2(y2, ylo, yhi);
                ull ylo2 = pack2(ylo), yhi2 = pack2(yhi);

                const ulonglong2* w0 = (const ulonglong2*)(sh_w + (2*p  )*64);
                const ulonglong2* w1 = (const ulonglong2*)(sh_w + (2*p+1)*64);
                #pragma unroll
                for (int q = 0; q < 16; q++) {
                    ulonglong2 a = w0[q];
                    pacc[2*q]   = ffma2(a.x, ylo2, pacc[2*q]);
                    pacc[2*q+1] = ffma2(a.y, ylo2, pacc[2*q+1]);
                }
                #pragma unroll
                for (int q = 0; q < 16; q++) {
                    ulonglong2 a = w1[q];
                    pacc[2*q]   = ffma2(a.x, yhi2, pacc[2*q]);
                    pacc[2*q+1] = ffma2(a.y, yhi2, pacc[2*q+1]);
                }
            }

            // reduce the two hid-halves via smem (overlay sh_h; safe post-sync)
            __syncthreads();
            ull* sh_red = sh_h;    // 32 x 256 ull = 64KB < sh_h size
            if (half == 1) {
                #pragma unroll
                for (int j = 0; j < 32; j++) sh_red[j*256 + pix] = pacc[j];
            }
            __syncthreads();
            if (half == 0) {
                const int gy = ty0 + p_iy, gx = tx0 + p_ix;
                float* op = out + (size_t)b * DIM * HW + gy*WW + gx;
                #pragma unroll
                for (int j = 0; j < 32; j++) {
                    ull v = add2(pacc[j], sh_red[j*256 + pix]);
                    float lo, hi;
                    unpack2(v, lo, hi);
                    op[(size_t)(2*j    ) * HW] = lo;
                    op[(size_t)(2*j + 1) * HW] = hi;
                }
            }
        }
        __syncthreads();   // before next tile restages sh_w / sh_ker2 / sh_h
    }

    // reset barrier state for the next graph replay (last CTA to finish)
    if (tid == 0) {
        __threadfence();
        if (atomicAdd(&g_done, 1u) == NB - 1u) {
            atomicExch(&g_bar1, 0u);
            atomicExch(&g_bar2, 0u);
            atomicExch(&g_done, 0u);
        }
    }
}

// ---------------------------------------------------------------------------
extern "C" void kernel_launch(void* const* d_in, const int* in_sizes, int n_in,
                              void* d_out, int out_size) {
    const float* x     = (const float*)d_in[0];
    const float* w_in  = (const float*)d_in[1];
    const float* b_in  = (const float*)d_in[2];
    const float* wg1   = (const float*)d_in[3];
    const float* bg1   = (const float*)d_in[4];
    const float* wg2   = (const float*)d_in[5];
    const float* bg2   = (const float*)d_in[6];
    const float* w_out = (const float*)d_in[7];
    const float* b_out = (const float*)d_in[8];
    float* out = (float*)d_out;

    int dev = 0, nsm = 148;
    cudaGetDevice(&dev);
    cudaDeviceGetAttribute(&nsm, cudaDevAttrMultiProcessorCount, dev);

    const int SMEM_BYTES = (8192 + 1152 + 128 + 64 + 64*NPIX*2) * 4; // 204,032 B
    cudaFuncSetAttribute(k_all, cudaFuncAttributeMaxDynamicSharedMemorySize, SMEM_BYTES);

    k_all<<<nsm, NT, SMEM_BYTES>>>(x, w_in, b_in, wg1, bg1, wg2, bg2, w_out, b_out, out);
}